// round 11
// baseline (speedup 1.0000x reference)
#include <cuda_runtime.h>
#include <math_constants.h>
#include <cstdint>

// Shapes: V=1024 fixed; B,L,T from in_sizes. Scratch for B<=64, T<=1024, S<=256.
#define VOCAB      1024
#define MAXB       64
#define MAXTP      1064          // padded T rows (((T+7)&~7) + 32)
#define SP         256           // padded extended-state stride (>= S = 2L+1), 8 per lane
#define NGRP       4             // smem ring groups
#define GROUP_BYTES (8 * SP * 4) // 8 rows/group = 8 KB
#define FULLMASK   0xffffffffu

#define LOG2E_F 1.4426950408889634f
#define LN2_F   0.6931471805599453f

typedef unsigned long long ull;

static __device__ __forceinline__ float fex2(float x) {
    float y; asm("ex2.approx.f32 %0, %1;" : "=f"(y) : "f"(x)); return y;
}

// Scratch: per-(b,t) extended-label PROBABILITIES (softmax, gathered), padded.
__device__ float g_p[(size_t)MAXB * MAXTP * SP];
__device__ float g_loss[MAXB];

// ---------------------------------------------------------------------------
// Pass 1: per-row softmax + gather. ONE WARP PER ROW (32 values/lane in
// registers, MLP=8), no SMEM, no CTA barriers. 8 rows per 256-thread CTA.
// (Exact R9 form — the ldcs variant regressed.)
// ---------------------------------------------------------------------------
__global__ void __launch_bounds__(256)
softmax_gather_kernel(const float* __restrict__ pred,
                      const int*   __restrict__ gt,
                      int NT, int T, int TP, int L, int S)
{
    const int row  = blockIdx.x * 8 + (threadIdx.x >> 5);
    if (row >= NT) return;
    const int lane = threadIdx.x & 31;
    const int b    = row / T;
    const int t    = row - b * T;

    const float* __restrict__ p = pred + (size_t)row * VOCAB;

    float4 v[8];
    #pragma unroll
    for (int k = 0; k < 8; k++)
        v[k] = *reinterpret_cast<const float4*>(p + lane * 4 + k * 128);

    float mx = -CUDART_INF_F;
    #pragma unroll
    for (int k = 0; k < 8; k++)
        mx = fmaxf(mx, fmaxf(fmaxf(v[k].x, v[k].y), fmaxf(v[k].z, v[k].w)));
    #pragma unroll
    for (int o = 16; o; o >>= 1)
        mx = fmaxf(mx, __shfl_xor_sync(FULLMASK, mx, o));
    const float c = mx * LOG2E_F;

    float sum = 0.f;
    #pragma unroll
    for (int k = 0; k < 8; k++) {
        sum += fex2(fmaf(v[k].x, LOG2E_F, -c)) + fex2(fmaf(v[k].y, LOG2E_F, -c))
             + fex2(fmaf(v[k].z, LOG2E_F, -c)) + fex2(fmaf(v[k].w, LOG2E_F, -c));
    }
    #pragma unroll
    for (int o = 16; o; o >>= 1)
        sum += __shfl_xor_sync(FULLMASK, sum, o);
    const float inv = __frcp_rn(sum);

    float* __restrict__ out = g_p + ((size_t)b * TP + t) * SP;
    const int* __restrict__ gtb = gt + (size_t)b * L;
    float val[8];
    #pragma unroll
    for (int j = 0; j < 8; j++) {
        int s = lane * 8 + j;
        float r = 0.f;
        if (s < S) {
            int lab = 0;
            if (s & 1) {
                int idx = (s >> 1); if (idx > L - 1) idx = L - 1;
                lab = gtb[idx];
            }
            r = fex2(fmaf(__ldg(p + lab), LOG2E_F, -c)) * inv;
        }
        val[j] = r;
    }
    *reinterpret_cast<float4*>(out + lane * 8)     = make_float4(val[0], val[1], val[2], val[3]);
    *reinterpret_cast<float4*>(out + lane * 8 + 4) = make_float4(val[4], val[5], val[6], val[7]);
}

// ---------------------------------------------------------------------------
// Pass 2: CTC forward recursion, prob domain, PER-LANE block floating point,
// renorm every 8 steps. One warp per CTA/batch; lane l owns states [8l,8l+8).
// Step math identical to R9 (proven 78 cyc/step); the p-row feed is now ONE
// cp.async.bulk of 8KB (8 rows) per 8 steps into a 4-group SMEM ring with
// mbarrier completion, filled 3 groups ahead — removing the 16 cyc/step
// LDGSTS issue tax of the per-step cp.async scheme.
// ---------------------------------------------------------------------------
__global__ void __launch_bounds__(32)
ctc_forward_kernel(const int* __restrict__ plen,
                   const int* __restrict__ gt,
                   const int* __restrict__ gtl,
                   int B, int T, int TP, int L, int S)
{
    __shared__ float ring[NGRP][8 * SP];   // 32 KB
    __shared__ ull   mbar[NGRP];

    const int b    = blockIdx.x;
    const int lane = threadIdx.x;
    const int ilen = min(plen[b], T);
    const int tl   = gtl[b];
    const float* __restrict__ gbase = g_p + (size_t)b * TP * SP;   // row base
    const int* __restrict__ gtb = gt + (size_t)b * L;

    const unsigned int ring_s = (unsigned int)__cvta_generic_to_shared(ring);
    const unsigned int mbar_s = (unsigned int)__cvta_generic_to_shared(mbar);

    // mbarrier init (lane 0), visible to async proxy before first bulk copy.
    if (lane == 0) {
        #pragma unroll
        for (int i = 0; i < NGRP; i++)
            asm volatile("mbarrier.init.shared.b64 [%0], 1;"
                         :: "r"(mbar_s + i * 8) : "memory");
        asm volatile("fence.proxy.async.shared::cta;" ::: "memory");
    }
    __syncwarp();

    // Skip masks for the 4 odd (label) states only; even states never skip.
    float m1, m3, m5, m7;
    {
        float mm[4];
        #pragma unroll
        for (int jj = 0; jj < 4; jj++) {
            int s = lane * 8 + 2 * jj + 1;
            float v = 0.f;
            if (s >= 2 && s < S) {
                int lab = gtb[s >> 1], lm2 = gtb[(s >> 1) - 1];
                v = (lab != 0 && lab != lm2) ? 1.f : 0.f;
            }
            mm[jj] = v;
        }
        m1 = mm[0]; m3 = mm[1]; m5 = mm[2]; m7 = mm[3];
    }

    const int nsteps = ilen - 1;           // recursion runs t = 1 .. ilen-1

    // fill(g): one 8KB bulk copy of rows [8g, 8g+8) into ring[g&3].
#define FILL(G)                                                             \
    do {                                                                     \
        if (lane == 0) {                                                     \
            int g_ = (G);                                                    \
            unsigned int mb = mbar_s + (g_ & (NGRP - 1)) * 8;                \
            asm volatile("mbarrier.arrive.expect_tx.shared.b64 _, [%0], %1;" \
                         :: "r"(mb), "r"((unsigned)GROUP_BYTES) : "memory"); \
            const float* src = gbase + (size_t)(g_ * 8) * SP;                \
            unsigned int dst = ring_s + (g_ & (NGRP - 1)) * GROUP_BYTES;     \
            asm volatile(                                                    \
                "cp.async.bulk.shared::cta.global.mbarrier::complete_tx::bytes" \
                " [%0], [%1], %2, [%3];"                                     \
                :: "r"(dst), "l"(src), "r"((unsigned)GROUP_BYTES), "r"(mb)   \
                : "memory");                                                 \
        }                                                                    \
    } while (0)

    // wait(g): all lanes wait for group g's bulk copy (parity (g>>2)&1).
#define GWAIT(G)                                                            \
    do {                                                                     \
        int g_ = (G);                                                        \
        unsigned int mb = mbar_s + (g_ & (NGRP - 1)) * 8;                    \
        unsigned int ph = (unsigned)((g_ >> 2) & 1);                         \
        asm volatile(                                                        \
            "{\n\t.reg .pred P;\n\t"                                         \
            "WL_%=:\n\t"                                                     \
            "mbarrier.try_wait.parity.acquire.cta.shared::cta.b64 P, [%0], %1, 0x989680;\n\t" \
            "@P bra.uni WD_%=;\n\t"                                          \
            "bra.uni WL_%=;\n\t"                                             \
            "WD_%=:\n\t}"                                                    \
            :: "r"(mb), "r"(ph) : "memory");                                 \
    } while (0)

    // LDS of row r for this lane (rows live in ring[(r>>3)&3][(r&7)*SP ..]).
#define LDROW(Q0, Q1, R)                                                    \
    do {                                                                     \
        int r_ = (R);                                                        \
        const float4* sp_ = reinterpret_cast<const float4*>(                 \
            &ring[(r_ >> 3) & (NGRP - 1)][(r_ & 7) * SP + lane * 8]);        \
        (Q0) = sp_[0]; (Q1) = sp_[1];                                        \
    } while (0)

#define CTC_STEP(Q0, Q1)                                                    \
    do {                                                                     \
        float u7 = __shfl_up_sync(FULLMASK, a[7], 1) * f;                    \
        float n0 = (a[0] + u7)                * (Q0).x;                      \
        float n1 = fmaf(m1, u7,   a[1] + a[0]) * (Q0).y;                     \
        float n2 = (a[2] + a[1])              * (Q0).z;                      \
        float n3 = fmaf(m3, a[1], a[3] + a[2]) * (Q0).w;                     \
        float n4 = (a[4] + a[3])              * (Q1).x;                      \
        float n5 = fmaf(m5, a[3], a[5] + a[4]) * (Q1).y;                     \
        float n6 = (a[6] + a[5])              * (Q1).z;                      \
        float n7 = fmaf(m7, a[5], a[7] + a[6]) * (Q1).w;                     \
        a[0]=n0; a[1]=n1; a[2]=n2; a[3]=n3; a[4]=n4; a[5]=n5; a[6]=n6; a[7]=n7; \
    } while (0)

#define CTC_RENORM()                                                        \
    do {                                                                     \
        float mx = fmaxf(fmaxf(fmaxf(a[0], a[1]), fmaxf(a[2], a[3])),       \
                         fmaxf(fmaxf(a[4], a[5]), fmaxf(a[6], a[7])));       \
        bool nz = (mx > 0.f);                                                \
        int  e  = nz ? ((__float_as_int(mx) >> 23) - 127) : 0;               \
        int  Elp = El + e;                                                   \
        int  Eleft = __shfl_up_sync(FULLMASK, Elp, 1);                       \
        if (!nz && lane > 0) Elp = Eleft;      /* adopt neighbor's scale */  \
        if (nz) {                                                            \
            float sc = __int_as_float((127 - e) << 23);                      \
            _Pragma("unroll")                                                \
            for (int j = 0; j < 8; j++) a[j] *= sc;                          \
        }                                                                    \
        El = Elp;                                                            \
        int El2 = __shfl_up_sync(FULLMASK, El, 1);                           \
        int dE  = El2 - El;                                                  \
        if (lane == 0 || dE < -126) f = 0.f;                                 \
        else f = __int_as_float((min(dE, 126) + 127) << 23);                 \
    } while (0)

    // Prologue: fill groups 0..2 (rows 0..23).
    FILL(0); FILL(1); FILL(2);

    int   El = 0;
    float f  = (lane == 0) ? 0.f : 1.f;
    float a[8];
    #pragma unroll
    for (int j = 0; j < 8; j++) a[j] = 0.f;

    // Group 0: alpha(t=0) from row 0, then steps t = 1..min(7, nsteps).
    GWAIT(0);
    FILL(3);
    float4 q0, q1;
    LDROW(q0, q1, 0);
    if (lane == 0) {
        a[0] = q0.x;
        a[1] = (tl > 0) ? q0.y : 0.f;
    }
    {
        int tlim0 = min(7, nsteps);
        if (nsteps >= 1) LDROW(q0, q1, 1);
        for (int t = 1; t <= tlim0; t++) {
            float4 nq0 = q0, nq1 = q1;
            if (t < 7) LDROW(nq0, nq1, t + 1);   // row <= 7: same group
            CTC_STEP(q0, q1);
            q0 = nq0; q1 = nq1;
        }
        if (tlim0 == 7) CTC_RENORM();
    }

    // Full groups: g covers steps t = 8g .. 8g+7.
    int g = 1;
    for (; 8 * g + 7 <= nsteps; g++) {
        GWAIT(g);
        FILL(g + 3);
        LDROW(q0, q1, 8 * g);
        #pragma unroll
        for (int k = 0; k < 8; k++) {
            float4 nq0 = q0, nq1 = q1;
            if (k < 7) LDROW(nq0, nq1, 8 * g + k + 1);
            CTC_STEP(q0, q1);
            if (k == 7) CTC_RENORM();
            q0 = nq0; q1 = nq1;
        }
    }
    // Tail: remaining steps all inside group g.
    {
        int t = 8 * g;
        if (t <= nsteps) {
            GWAIT(g);
            LDROW(q0, q1, t);
            for (; t <= nsteps; t++) {
                float4 nq0 = q0, nq1 = q1;
                if (t + 1 <= nsteps) LDROW(nq0, nq1, t + 1);
                CTC_STEP(q0, q1);
                q0 = nq0; q1 = nq1;
            }
        }
    }
#undef CTC_STEP
#undef CTC_RENORM
#undef FILL
#undef GWAIT
#undef LDROW

    // end_ll over alpha[2*tl] and alpha[max(2*tl-1,0)]
    int s1 = 2 * tl;
    int s2 = (2 * tl - 1 > 0) ? (2 * tl - 1) : 0;
    int lane1 = s1 >> 3, slot1 = s1 & 7;
    int lane2 = s2 >> 3, slot2 = s2 & 7;
    float v1 = a[0], v2 = a[0];
    #pragma unroll
    for (int j = 1; j < 8; j++) { v1 = (slot1 == j) ? a[j] : v1;
                                  v2 = (slot2 == j) ? a[j] : v2; }
    int   E1 = __shfl_sync(FULLMASK, El, lane1);
    int   E2 = __shfl_sync(FULLMASK, El, lane2);
    v1 = __shfl_sync(FULLMASK, v1, lane1);
    v2 = __shfl_sync(FULLMASK, v2, lane2);

    if (lane == 0) {
        float l1 = (v1 > 0.f) ? (log2f(v1) + (float)E1) : -3.0e38f;
        float l2 = (v2 > 0.f) ? (log2f(v2) + (float)E2) : -3.0e38f;
        float mx = fmaxf(l1, l2);
        float loss;
        if (mx < -2.0e38f) {
            loss = 0.f;                    // zero_infinity: p == 0
        } else {
            float tot2 = mx + log2f(exp2f(l1 - mx) + exp2f(l2 - mx));
            loss = -tot2 * LN2_F;
        }
        g_loss[b] = loss / (float)tl;
    }
}

// ---------------------------------------------------------------------------
// Pass 3: deterministic batch-mean reduction (single warp).
// ---------------------------------------------------------------------------
__global__ void reduce_loss_kernel(float* __restrict__ out, int B)
{
    float v = 0.f;
    for (int i = threadIdx.x; i < B; i += 32) v += g_loss[i];
    #pragma unroll
    for (int o = 16; o; o >>= 1) v += __shfl_xor_sync(FULLMASK, v, o);
    if (threadIdx.x == 0) out[0] = v / (float)B;
}

// ---------------------------------------------------------------------------
extern "C" void kernel_launch(void* const* d_in, const int* in_sizes, int n_in,
                              void* d_out, int out_size)
{
    const float* pred = (const float*)d_in[0];
    const int*   plen = (const int*)d_in[1];
    const int*   gt   = (const int*)d_in[2];
    const int*   gtl  = (const int*)d_in[3];

    const int B  = in_sizes[1];
    const int L  = in_sizes[2] / B;
    const int T  = in_sizes[0] / (B * VOCAB);
    const int S  = 2 * L + 1;
    const int TP = ((T + 7) & ~7) + 32;   // group-aligned + fill slack
    const int NT = B * T;

    softmax_gather_kernel<<<(NT + 7) / 8, 256>>>(pred, gt, NT, T, TP, L, S);
    ctc_forward_kernel<<<B, 32>>>(plen, gt, gtl, B, T, TP, L, S);
    reduce_loss_kernel<<<1, 32>>>((float*)d_out, B);
}

// round 13
// speedup vs baseline: 1.1449x; 1.1449x over previous
#include <cuda_runtime.h>
#include <math_constants.h>
#include <cstdint>

// Shapes: V=1024 fixed; B,L,T from in_sizes. Scratch for B<=64, T<=1024, S<=256.
#define VOCAB      1024
#define MAXB       64
#define MAXTP      1056          // padded T rows (T + 32 prefetch slack)
#define SP         256           // padded extended-state stride (>= S = 2L+1), 8 per lane
#define RING       32            // smem ring slots (rows) per warp
#define DIST       28            // prefetch distance (rows ahead)
#define FULLMASK   0xffffffffu

#define LOG2E_F 1.4426950408889634f
#define LN2_F   0.6931471805599453f

typedef unsigned long long ull;

static __device__ __forceinline__ float fex2(float x) {
    float y; asm("ex2.approx.f32 %0, %1;" : "=f"(y) : "f"(x)); return y;
}
// a + b as FFMA-imm (rt_SMSP=1 vs FADD's 2): d = a*1.0f + b, exact.
static __device__ __forceinline__ float fadd1(float a, float b) {
    float d; asm("fma.rn.f32 %0, %1, 0f3F800000, %2;" : "=f"(d) : "f"(a), "f"(b));
    return d;
}

#define CP16(sm, gp) \
    asm volatile("cp.async.cg.shared.global [%0], [%1], 16;" :: "r"(sm), "l"(gp))
#define CP_COMMIT() \
    asm volatile("cp.async.commit_group;" ::: "memory")
#define CP_WAIT_26() \
    asm volatile("cp.async.wait_group 26;" ::: "memory")
#define CP_WAIT_27() \
    asm volatile("cp.async.wait_group 27;" ::: "memory")
#define CP_WAIT_ALL() \
    asm volatile("cp.async.wait_all;" ::: "memory")

// Scratch: per-(b,t) extended-label PROBABILITIES (softmax, gathered), padded.
__device__ float g_p[(size_t)MAXB * MAXTP * SP];
__device__ float g_loss[MAXB];

// ---------------------------------------------------------------------------
// Pass 1: per-row softmax + gather. ONE WARP PER ROW (32 values/lane in
// registers, MLP=8), no SMEM, no CTA barriers. 8 rows per 256-thread CTA.
// (Exact R9 form — proven.)
// ---------------------------------------------------------------------------
__global__ void __launch_bounds__(256)
softmax_gather_kernel(const float* __restrict__ pred,
                      const int*   __restrict__ gt,
                      int NT, int T, int TP, int L, int S)
{
    const int row  = blockIdx.x * 8 + (threadIdx.x >> 5);
    if (row >= NT) return;
    const int lane = threadIdx.x & 31;
    const int b    = row / T;
    const int t    = row - b * T;

    const float* __restrict__ p = pred + (size_t)row * VOCAB;

    float4 v[8];
    #pragma unroll
    for (int k = 0; k < 8; k++)
        v[k] = *reinterpret_cast<const float4*>(p + lane * 4 + k * 128);

    float mx = -CUDART_INF_F;
    #pragma unroll
    for (int k = 0; k < 8; k++)
        mx = fmaxf(mx, fmaxf(fmaxf(v[k].x, v[k].y), fmaxf(v[k].z, v[k].w)));
    #pragma unroll
    for (int o = 16; o; o >>= 1)
        mx = fmaxf(mx, __shfl_xor_sync(FULLMASK, mx, o));
    const float c = mx * LOG2E_F;

    float sum = 0.f;
    #pragma unroll
    for (int k = 0; k < 8; k++) {
        sum += fex2(fmaf(v[k].x, LOG2E_F, -c)) + fex2(fmaf(v[k].y, LOG2E_F, -c))
             + fex2(fmaf(v[k].z, LOG2E_F, -c)) + fex2(fmaf(v[k].w, LOG2E_F, -c));
    }
    #pragma unroll
    for (int o = 16; o; o >>= 1)
        sum += __shfl_xor_sync(FULLMASK, sum, o);
    const float inv = __frcp_rn(sum);

    float* __restrict__ out = g_p + ((size_t)b * TP + t) * SP;
    const int* __restrict__ gtb = gt + (size_t)b * L;
    float val[8];
    #pragma unroll
    for (int j = 0; j < 8; j++) {
        int s = lane * 8 + j;
        float r = 0.f;
        if (s < S) {
            int lab = 0;
            if (s & 1) {
                int idx = (s >> 1); if (idx > L - 1) idx = L - 1;
                lab = gtb[idx];
            }
            r = fex2(fmaf(__ldg(p + lab), LOG2E_F, -c)) * inv;
        }
        val[j] = r;
    }
    *reinterpret_cast<float4*>(out + lane * 8)     = make_float4(val[0], val[1], val[2], val[3]);
    *reinterpret_cast<float4*>(out + lane * 8 + 4) = make_float4(val[4], val[5], val[6], val[7]);
}

// ---------------------------------------------------------------------------
// Pass 2: CTC forward recursion, prob domain, PER-LANE block floating point,
// renorm every 8 steps (R9's proven TWO-SHUFFLE renorm: the carried factor f
// must use the left lane's FINAL post-adoption exponent — a zero left lane
// adopts its own left's frame and can become nonzero mid-block).
// Single change vs R9: the 8 two-operand adds per step use FFMA-imm
// (rt_SMSP 1 vs FADD's 2), which is bit-exact.
// cp.async SMEM ring (depth 28) hides DRAM latency on evicted g_p.
// ---------------------------------------------------------------------------
__global__ void __launch_bounds__(32)
ctc_forward_kernel(const int* __restrict__ plen,
                   const int* __restrict__ gt,
                   const int* __restrict__ gtl,
                   int B, int T, int TP, int L, int S)
{
    __shared__ float ring[RING][SP];     // 32 KB

    const int b    = blockIdx.x;
    const int lane = threadIdx.x;
    const int ilen = min(plen[b], T);
    const int tl   = gtl[b];
    const float* __restrict__ Pb = g_p + (size_t)b * TP * SP + lane * 8;
    const int* __restrict__ gtb = gt + (size_t)b * L;
    const unsigned int rb =
        (unsigned int)__cvta_generic_to_shared(ring) + (unsigned int)(lane * 32);

    // Skip masks for the 4 odd (label) states only; even states never skip.
    float m1, m3, m5, m7;
    {
        float mm[4];
        #pragma unroll
        for (int jj = 0; jj < 4; jj++) {
            int s = lane * 8 + 2 * jj + 1;
            float v = 0.f;
            if (s >= 2 && s < S) {
                int lab = gtb[s >> 1], lm2 = gtb[(s >> 1) - 1];
                v = (lab != 0 && lab != lm2) ? 1.f : 0.f;
            }
            mm[jj] = v;
        }
        m1 = mm[0]; m3 = mm[1]; m5 = mm[2]; m7 = mm[3];
    }

    // alpha(t=0)
    float a[8];
    #pragma unroll
    for (int j = 0; j < 8; j++) a[j] = 0.f;
    if (lane == 0) {
        float4 q = *reinterpret_cast<const float4*>(Pb);
        a[0] = q.x;
        a[1] = (tl > 0) ? q.y : 0.f;
    }

    int   El = 0;                          // per-lane exponent
    float f  = (lane == 0) ? 0.f : 1.f;    // 2^(El_left - El); lane 0 has no left
    const int nsteps = ilen - 1;           // recursion runs t = 1 .. ilen-1

#define CTC_STEP(Q0, Q1)                                                    \
    do {                                                                     \
        float u7  = __shfl_up_sync(FULLMASK, a[7], 1);                       \
        float u7f = u7 * f;                                                  \
        float n0 = fadd1(a[0], u7f)                 * (Q0).x;                \
        float n1 = fmaf(m1, u7f,  fadd1(a[1], a[0])) * (Q0).y;               \
        float n2 = fadd1(a[2], a[1])                * (Q0).z;                \
        float n3 = fmaf(m3, a[1], fadd1(a[3], a[2])) * (Q0).w;               \
        float n4 = fadd1(a[4], a[3])                * (Q1).x;                \
        float n5 = fmaf(m5, a[3], fadd1(a[5], a[4])) * (Q1).y;               \
        float n6 = fadd1(a[6], a[5])                * (Q1).z;                \
        float n7 = fmaf(m7, a[5], fadd1(a[7], a[6])) * (Q1).w;               \
        a[0]=n0; a[1]=n1; a[2]=n2; a[3]=n3; a[4]=n4; a[5]=n5; a[6]=n6; a[7]=n7; \
    } while (0)

    // R9 renorm: two shuffles (adoption from left's Elp; f from left's FINAL El).
#define CTC_RENORM()                                                        \
    do {                                                                     \
        float mx = fmaxf(fmaxf(fmaxf(a[0], a[1]), fmaxf(a[2], a[3])),       \
                         fmaxf(fmaxf(a[4], a[5]), fmaxf(a[6], a[7])));       \
        bool nz = (mx > 0.f);                                                \
        int  e  = nz ? ((__float_as_int(mx) >> 23) - 127) : 0;               \
        int  Elp = El + e;                                                   \
        int  Eleft = __shfl_up_sync(FULLMASK, Elp, 1);                       \
        if (!nz && lane > 0) Elp = Eleft;      /* adopt neighbor's scale */  \
        if (nz) {                                                            \
            float sc = __int_as_float((127 - e) << 23);                      \
            _Pragma("unroll")                                                \
            for (int j = 0; j < 8; j++) a[j] *= sc;                          \
        }                                                                    \
        El = Elp;                                                            \
        int El2 = __shfl_up_sync(FULLMASK, El, 1);                           \
        int dE  = El2 - El;                                                  \
        if (lane == 0 || dE < -126) f = 0.f;                                 \
        else f = __int_as_float((min(dE, 126) + 127) << 23);                 \
    } while (0)

    // Prologue: fill ring with rows 1..DIST
    {
        const float* gp = Pb + SP;           // row 1
        #pragma unroll 4
        for (int r = 1; r <= DIST; r++) {
            unsigned int sa = rb + (unsigned int)((r & (RING - 1)) * (SP * 4));
            CP16(sa, gp); CP16(sa + 16, gp + 4);
            CP_COMMIT();
            gp += SP;
        }
    }

    float4 q0 = make_float4(0.f, 0.f, 0.f, 0.f), q1 = q0;
    if (nsteps >= 1) {
        CP_WAIT_27();                        // row 1 landed
        const float4* sp = reinterpret_cast<const float4*>(&ring[1][lane * 8]);
        q0 = sp[0]; q1 = sp[1];
    }

    const float* fill_ptr = Pb + (size_t)(1 + DIST) * SP;
    int t = 1;
    for (; t + 7 <= nsteps; t += 8) {
        #pragma unroll
        for (int k = 0; k < 8; k++) {
            CP_WAIT_26();                    // row t+k+1 landed
            int nslot = (t + k + 1) & (RING - 1);
            const float4* sp = reinterpret_cast<const float4*>(&ring[nslot][lane * 8]);
            float4 nq0 = sp[0], nq1 = sp[1];
            // refill: row t+k+DIST into its slot
            {
                unsigned int sa = rb +
                    (unsigned int)((((t + k + DIST) & (RING - 1))) * (SP * 4));
                const float* gp = fill_ptr + (size_t)k * SP;
                CP16(sa, gp); CP16(sa + 16, gp + 4);
                CP_COMMIT();
            }
            CTC_STEP(q0, q1);
            if (k == 7) CTC_RENORM();
            q0 = nq0; q1 = nq1;
        }
        fill_ptr += 8 * SP;
    }
    // Tail: all remaining rows were prefetched into the ring already.
    if (t <= nsteps) {
        CP_WAIT_ALL();
        for (; t <= nsteps; t++) {
            CTC_STEP(q0, q1);
            int nslot = (t + 1) & (RING - 1);   // contents unused past nsteps
            const float4* sp = reinterpret_cast<const float4*>(&ring[nslot][lane * 8]);
            q0 = sp[0]; q1 = sp[1];
        }
    }
#undef CTC_STEP
#undef CTC_RENORM

    // end_ll over alpha[2*tl] and alpha[max(2*tl-1,0)]
    int s1 = 2 * tl;
    int s2 = (2 * tl - 1 > 0) ? (2 * tl - 1) : 0;
    int lane1 = s1 >> 3, slot1 = s1 & 7;
    int lane2 = s2 >> 3, slot2 = s2 & 7;
    float v1 = a[0], v2 = a[0];
    #pragma unroll
    for (int j = 1; j < 8; j++) { v1 = (slot1 == j) ? a[j] : v1;
                                  v2 = (slot2 == j) ? a[j] : v2; }
    int   E1 = __shfl_sync(FULLMASK, El, lane1);
    int   E2 = __shfl_sync(FULLMASK, El, lane2);
    v1 = __shfl_sync(FULLMASK, v1, lane1);
    v2 = __shfl_sync(FULLMASK, v2, lane2);

    if (lane == 0) {
        float l1 = (v1 > 0.f) ? (log2f(v1) + (float)E1) : -3.0e38f;
        float l2 = (v2 > 0.f) ? (log2f(v2) + (float)E2) : -3.0e38f;
        float mx = fmaxf(l1, l2);
        float loss;
        if (mx < -2.0e38f) {
            loss = 0.f;                    // zero_infinity: p == 0
        } else {
            float tot2 = mx + log2f(exp2f(l1 - mx) + exp2f(l2 - mx));
            loss = -tot2 * LN2_F;
        }
        g_loss[b] = loss / (float)tl;
    }
}

// ---------------------------------------------------------------------------
// Pass 3: deterministic batch-mean reduction (single warp).
// ---------------------------------------------------------------------------
__global__ void reduce_loss_kernel(float* __restrict__ out, int B)
{
    float v = 0.f;
    for (int i = threadIdx.x; i < B; i += 32) v += g_loss[i];
    #pragma unroll
    for (int o = 16; o; o >>= 1) v += __shfl_xor_sync(FULLMASK, v, o);
    if (threadIdx.x == 0) out[0] = v / (float)B;
}

// ---------------------------------------------------------------------------
extern "C" void kernel_launch(void* const* d_in, const int* in_sizes, int n_in,
                              void* d_out, int out_size)
{
    const float* pred = (const float*)d_in[0];
    const int*   plen = (const int*)d_in[1];
    const int*   gt   = (const int*)d_in[2];
    const int*   gtl  = (const int*)d_in[3];

    const int B  = in_sizes[1];
    const int L  = in_sizes[2] / B;
    const int T  = in_sizes[0] / (B * VOCAB);
    const int S  = 2 * L + 1;
    const int TP = T + 32;                // padded rows (prefetch slack)
    const int NT = B * T;

    softmax_gather_kernel<<<(NT + 7) / 8, 256>>>(pred, gt, NT, T, TP, L, S);
    ctc_forward_kernel<<<B, 32>>>(plen, gt, gtl, B, T, TP, L, S);
    reduce_loss_kernel<<<1, 32>>>((float*)d_out, B);
}